// round 10
// baseline (speedup 1.0000x reference)
#include <cuda_runtime.h>
#include <cstdint>

#define S_  16
#define T_  400
#define F_  16
#define SF_ 250
#define G_  4
#define H1  32
#define H2  16

#define OBS_STRIDE 20                 // words; 80 bytes per row
#define THREADS    256
#define R_         4
#define CHUNKS     9
#define ROWS_S     (T_ * (SF_ + 1))                    // 100400
#define ROWS_CTA   ((ROWS_S + CHUNKS - 1) / CHUNKS)    // 11156

typedef unsigned long long ull;

__device__ __forceinline__ ull pk2(float a, float b) {
    ull r; asm("mov.b64 %0, {%1,%2};" : "=l"(r) : "f"(a), "f"(b)); return r;
}
__device__ __forceinline__ void upk(ull p, float& a, float& b) {
    asm("mov.b64 {%0,%1}, %2;" : "=f"(a), "=f"(b) : "l"(p));
}
__device__ __forceinline__ ull fma2(ull a, ull b, ull c) {
    ull d; asm("fma.rn.f32x2 %0, %1, %2, %3;" : "=l"(d) : "l"(a), "l"(b), "l"(c)); return d;
}
__device__ __forceinline__ float lrelu(float x) { return fmaxf(x, 0.01f * x); }

struct RowIdx { int off[G_]; };   // byte offsets into sObs for each group row

__device__ __forceinline__ RowIdx load_idx(const int* __restrict__ perm, int s, int idx) {
    RowIdx r;
    int sfp = idx / T_;
    int t   = idx - sfp * T_;
    if (sfp == 0) {
        int o = t * (OBS_STRIDE * 4);
        r.off[0] = r.off[1] = r.off[2] = r.off[3] = o;
    } else {
        int base = ((sfp - 1) * (G_ * S_) + s) * T_ + t;
        r.off[0] = perm[base] * (OBS_STRIDE * 4);
        r.off[1] = perm[base + S_ * T_] * (OBS_STRIDE * 4);
        r.off[2] = perm[base + 2 * S_ * T_] * (OBS_STRIDE * 4);
        r.off[3] = perm[base + 3 * S_ * T_] * (OBS_STRIDE * 4);
    }
    return r;
}

__global__ __launch_bounds__(THREADS, 1)
void fused_kernel(const float* __restrict__ obs,
                  const float* __restrict__ mu,
                  const float* __restrict__ Sig,
                  const int*   __restrict__ perm,
                  const float* __restrict__ W1,
                  const float* __restrict__ b1,
                  const float* __restrict__ W2,
                  const float* __restrict__ b2,
                  const float* __restrict__ W3,
                  const float* __restrict__ b3,
                  float* __restrict__ out) {
    __shared__ __align__(16) float sObs[T_ * OBS_STRIDE];  // 32000 B
    __shared__ __align__(16) float sW1[F_ * H1];           // W1eff [j][c]
    __shared__ __align__(16) float sW2[H1 * H2];           // [i][j]
    __shared__ __align__(16) float sB1[H1];
    __shared__ __align__(16) float sB2[H2];
    __shared__ __align__(16) float sW3[H2];

    const int s   = blockIdx.y;
    const int k   = blockIdx.x;
    const int tid = threadIdx.x;

    // ---- stage obs slice (padded rows) ----
    const float4* osrc = (const float4*)(obs + s * (T_ * F_));
    for (int m = tid; m < T_ * F_ / 4; m += THREADS) {
        int t = m >> 2, q = m & 3;
        *(float4*)(sObs + t * OBS_STRIDE + q * 4) = osrc[m];
    }
    // ---- W1eff = Sigma^T W1 (normalize folded into layer 1) ----
    for (int m = tid; m < F_ * H1; m += THREADS) {
        int j = m >> 5, c = m & 31;
        float acc = 0.f;
        #pragma unroll
        for (int i = 0; i < F_; i++) acc += Sig[i * F_ + j] * W1[i * H1 + c];
        sW1[j * H1 + c] = acc;
    }
    // ---- b1eff = b1 - mu^T W1eff ----
    if (tid < H1) {
        int c = tid;
        float bacc = 0.f;
        #pragma unroll
        for (int j = 0; j < F_; j++) {
            float wj = 0.f;
            #pragma unroll
            for (int i = 0; i < F_; i++) wj += Sig[i * F_ + j] * W1[i * H1 + c];
            bacc += mu[j] * wj;
        }
        sB1[c] = b1[c] - bacc;
    }
    for (int m = tid; m < H1 * H2; m += THREADS) sW2[m] = W2[m];
    if (tid < H2) sB2[tid] = b2[tid];
    if (tid < H2) sW3[tid] = W3[tid];
    __syncthreads();

    const float b3v = b3[0];
    const int rowsBeg = k * ROWS_CTA;
    const int rowsEnd = (rowsBeg + ROWS_CTA < ROWS_S) ? rowsBeg + ROWS_CTA : ROWS_S;
    float* outS = out + s * ROWS_S;
    const char* obsB = (const char*)sObs;

    int idx0 = rowsBeg + tid;
    if (idx0 >= rowsEnd) return;

    RowIdx ra[R_];
    #pragma unroll
    for (int r = 0; r < R_; r++) {
        int id = idx0 + r * THREADS;
        ra[r] = load_idx(perm, s, id < rowsEnd ? id : rowsEnd - 1);
    }

    while (true) {
        const int curBase = idx0;
        RowIdx ci[R_];
        #pragma unroll
        for (int r = 0; r < R_; r++) ci[r] = ra[r];

        // ---- prefetch next iteration's perm indices ----
        idx0 += R_ * THREADS;
        const bool more = (idx0 < rowsEnd);
        if (more) {
            #pragma unroll
            for (int r = 0; r < R_; r++) {
                int id = idx0 + r * THREADS;
                ra[r] = load_idx(perm, s, id < rowsEnd ? id : rowsEnd - 1);
            }
        }

        // ---- layer-2 accumulators (init with b2) ----
        ull c2[R_][8];
        {
            const ull* pb = (const ull*)sB2;
            #pragma unroll
            for (int r = 0; r < R_; r++)
                #pragma unroll
                for (int p = 0; p < 8; p++) c2[r][p] = pb[p];
        }

        #pragma unroll
        for (int half = 0; half < 2; half++) {
            // ======== LAYER 1 (software-pipelined weights + gathers) ========
            ull h[R_][8];
            {
                const ull* pb = (const ull*)(sB1 + half * 16);
                #pragma unroll
                for (int r = 0; r < R_; r++)
                    #pragma unroll
                    for (int p = 0; p < 8; p++) h[r][p] = pb[p];
            }

            float4 xb[2][R_];       // double-buffered gathers (per g)
            ulonglong2 wb[2][4];    // double-buffered weight blocks (per (g,jj))

            // prime: gather g=0, weights block 0
            #pragma unroll
            for (int r = 0; r < R_; r++)
                xb[0][r] = *(const float4*)(obsB + ci[r].off[0] + 0 * 16);
            {
                const ulonglong2* w = (const ulonglong2*)(sW1 + 0 * H1 + half * 16);
                wb[0][0] = w[0]; wb[0][1] = w[1]; wb[0][2] = w[2]; wb[0][3] = w[3];
            }

            #pragma unroll
            for (int g = 0; g < G_; g++) {
                // prefetch next g's gathers
                if (g < G_ - 1) {
                    #pragma unroll
                    for (int r = 0; r < R_; r++)
                        xb[(g + 1) & 1][r] =
                            *(const float4*)(obsB + ci[r].off[g + 1] + (g + 1) * 16);
                }
                #pragma unroll
                for (int jj = 0; jj < 4; jj++) {
                    const int b = 4 * g + jj;
                    // prefetch next weight block
                    if (b < 15) {
                        const ulonglong2* w =
                            (const ulonglong2*)(sW1 + (b + 1) * H1 + half * 16);
                        wb[(b + 1) & 1][0] = w[0];
                        wb[(b + 1) & 1][1] = w[1];
                        wb[(b + 1) & 1][2] = w[2];
                        wb[(b + 1) & 1][3] = w[3];
                    }
                    const ulonglong2* wc = wb[b & 1];
                    ulonglong2 w0 = wc[0], w1 = wc[1], w2 = wc[2], w3 = wc[3];
                    #pragma unroll
                    for (int r = 0; r < R_; r++) {
                        float4 xq = xb[g & 1][r];
                        float xs = (jj == 0) ? xq.x : (jj == 1) ? xq.y
                                 : (jj == 2) ? xq.z : xq.w;
                        ull xj = pk2(xs, xs);
                        h[r][0] = fma2(xj, w0.x, h[r][0]);
                        h[r][1] = fma2(xj, w0.y, h[r][1]);
                        h[r][2] = fma2(xj, w1.x, h[r][2]);
                        h[r][3] = fma2(xj, w1.y, h[r][3]);
                        h[r][4] = fma2(xj, w2.x, h[r][4]);
                        h[r][5] = fma2(xj, w2.y, h[r][5]);
                        h[r][6] = fma2(xj, w3.x, h[r][6]);
                        h[r][7] = fma2(xj, w3.y, h[r][7]);
                    }
                }
            }

            // ======== LAYER 2 (software-pipelined weights) ========
            ulonglong2 w2b[2][8];   // [par][0..3]=u row, [4..7]=v row
            {
                const int i0 = half * 16;
                const ulonglong2* wu = (const ulonglong2*)(sW2 + i0 * H2);
                const ulonglong2* wv = (const ulonglong2*)(sW2 + (i0 + 1) * H2);
                #pragma unroll
                for (int q = 0; q < 4; q++) { w2b[0][q] = wu[q]; w2b[0][4 + q] = wv[q]; }
            }
            #pragma unroll
            for (int p = 0; p < 8; p++) {
                if (p < 7) {
                    const int i0 = half * 16 + 2 * (p + 1);
                    const ulonglong2* wu = (const ulonglong2*)(sW2 + i0 * H2);
                    const ulonglong2* wv = (const ulonglong2*)(sW2 + (i0 + 1) * H2);
                    #pragma unroll
                    for (int q = 0; q < 4; q++) {
                        w2b[(p + 1) & 1][q] = wu[q];
                        w2b[(p + 1) & 1][4 + q] = wv[q];
                    }
                }
                const ulonglong2* wc = w2b[p & 1];
                ulonglong2 u0 = wc[0], u1 = wc[1], u2 = wc[2], u3 = wc[3];
                ulonglong2 v0 = wc[4], v1 = wc[5], v2 = wc[6], v3 = wc[7];
                #pragma unroll
                for (int r = 0; r < R_; r++) {
                    float a, b;
                    upk(h[r][p], a, b);
                    float au = lrelu(a), av = lrelu(b);
                    ull au2 = pk2(au, au), av2 = pk2(av, av);
                    c2[r][0] = fma2(au2, u0.x, c2[r][0]);
                    c2[r][1] = fma2(au2, u0.y, c2[r][1]);
                    c2[r][2] = fma2(au2, u1.x, c2[r][2]);
                    c2[r][3] = fma2(au2, u1.y, c2[r][3]);
                    c2[r][4] = fma2(au2, u2.x, c2[r][4]);
                    c2[r][5] = fma2(au2, u2.y, c2[r][5]);
                    c2[r][6] = fma2(au2, u3.x, c2[r][6]);
                    c2[r][7] = fma2(au2, u3.y, c2[r][7]);
                    c2[r][0] = fma2(av2, v0.x, c2[r][0]);
                    c2[r][1] = fma2(av2, v0.y, c2[r][1]);
                    c2[r][2] = fma2(av2, v1.x, c2[r][2]);
                    c2[r][3] = fma2(av2, v1.y, c2[r][3]);
                    c2[r][4] = fma2(av2, v2.x, c2[r][4]);
                    c2[r][5] = fma2(av2, v2.y, c2[r][5]);
                    c2[r][6] = fma2(av2, v3.x, c2[r][6]);
                    c2[r][7] = fma2(av2, v3.y, c2[r][7]);
                }
            }
        }

        // ---- layer 3 + sigmoid + guarded store (two partial sums per row) ----
        #pragma unroll
        for (int r = 0; r < R_; r++) {
            float z0 = b3v, z1 = 0.f;
            #pragma unroll
            for (int p = 0; p < 8; p++) {
                float u, v;
                upk(c2[r][p], u, v);
                z0 += lrelu(u) * sW3[2 * p];
                z1 += lrelu(v) * sW3[2 * p + 1];
            }
            float z = z0 + z1;
            int cid = curBase + r * THREADS;
            if (cid < rowsEnd) outS[cid] = 1.f / (1.f + __expf(-z));
        }

        if (!more) break;
    }
}

extern "C" void kernel_launch(void* const* d_in, const int* in_sizes, int n_in,
                              void* d_out, int out_size) {
    const float* obs  = (const float*)d_in[0];
    const float* mu   = (const float*)d_in[1];
    const float* Sig  = (const float*)d_in[2];
    const int*   perm = (const int*)d_in[3];
    const float* W1   = (const float*)d_in[4];
    const float* b1   = (const float*)d_in[5];
    const float* W2   = (const float*)d_in[6];
    const float* b2   = (const float*)d_in[7];
    const float* W3   = (const float*)d_in[8];
    const float* b3   = (const float*)d_in[9];
    float* out = (float*)d_out;

    dim3 grid(CHUNKS, S_);
    fused_kernel<<<grid, THREADS>>>(obs, mu, Sig, perm, W1, b1, W2, b2, W3, b3, out);
}

// round 11
// speedup vs baseline: 1.0311x; 1.0311x over previous
#include <cuda_runtime.h>
#include <cstdint>

#define S_  16
#define T_  400
#define F_  16
#define SF_ 250
#define G_  4
#define H1  32
#define H2  16

#define OBS_STRIDE 20                 // words; 80 bytes per row
#define THREADS    384
#define R_         3
#define CHUNKS     9
#define ROWS_S     (T_ * (SF_ + 1))                    // 100400
#define ROWS_CTA   ((ROWS_S + CHUNKS - 1) / CHUNKS)    // 11156

typedef unsigned long long ull;

__device__ __forceinline__ ull pk2(float a, float b) {
    ull r; asm("mov.b64 %0, {%1,%2};" : "=l"(r) : "f"(a), "f"(b)); return r;
}
__device__ __forceinline__ void upk(ull p, float& a, float& b) {
    asm("mov.b64 {%0,%1}, %2;" : "=f"(a), "=f"(b) : "l"(p));
}
__device__ __forceinline__ ull fma2(ull a, ull b, ull c) {
    ull d; asm("fma.rn.f32x2 %0, %1, %2, %3;" : "=l"(d) : "l"(a), "l"(b), "l"(c)); return d;
}
__device__ __forceinline__ float lrelu(float x) { return fmaxf(x, 0.01f * x); }

struct RowIdx { int off[G_]; };   // byte offsets into sObs for each group row

__device__ __forceinline__ RowIdx load_idx(const int* __restrict__ perm, int s, int idx) {
    RowIdx r;
    int sfp = idx / T_;
    int t   = idx - sfp * T_;
    if (sfp == 0) {
        int o = t * (OBS_STRIDE * 4);
        r.off[0] = r.off[1] = r.off[2] = r.off[3] = o;
    } else {
        int base = ((sfp - 1) * (G_ * S_) + s) * T_ + t;
        r.off[0] = perm[base] * (OBS_STRIDE * 4);
        r.off[1] = perm[base + S_ * T_] * (OBS_STRIDE * 4);
        r.off[2] = perm[base + 2 * S_ * T_] * (OBS_STRIDE * 4);
        r.off[3] = perm[base + 3 * S_ * T_] * (OBS_STRIDE * 4);
    }
    return r;
}

__global__ __launch_bounds__(THREADS, 1)
void fused_kernel(const float* __restrict__ obs,
                  const float* __restrict__ mu,
                  const float* __restrict__ Sig,
                  const int*   __restrict__ perm,
                  const float* __restrict__ W1,
                  const float* __restrict__ b1,
                  const float* __restrict__ W2,
                  const float* __restrict__ b2,
                  const float* __restrict__ W3,
                  const float* __restrict__ b3,
                  float* __restrict__ out) {
    __shared__ __align__(16) float sObs[T_ * OBS_STRIDE];  // 32000 B
    __shared__ __align__(16) float sW1[F_ * H1];           // W1eff [j][c]
    __shared__ __align__(16) float sW2[H1 * H2];           // [i][j]
    __shared__ __align__(16) float sB1[H1];
    __shared__ __align__(16) float sB2[H2];
    __shared__ __align__(16) float sW3[H2];

    const int s   = blockIdx.y;
    const int k   = blockIdx.x;
    const int tid = threadIdx.x;

    // ---- stage obs slice (padded rows) ----
    const float4* osrc = (const float4*)(obs + s * (T_ * F_));
    for (int m = tid; m < T_ * F_ / 4; m += THREADS) {
        int t = m >> 2, q = m & 3;
        *(float4*)(sObs + t * OBS_STRIDE + q * 4) = osrc[m];
    }
    // ---- W1eff = Sigma^T W1 (normalize folded into layer 1) ----
    for (int m = tid; m < F_ * H1; m += THREADS) {
        int j = m >> 5, c = m & 31;
        float acc = 0.f;
        #pragma unroll
        for (int i = 0; i < F_; i++) acc += Sig[i * F_ + j] * W1[i * H1 + c];
        sW1[j * H1 + c] = acc;
    }
    // ---- b1eff = b1 - mu^T W1eff ----
    if (tid < H1) {
        int c = tid;
        float bacc = 0.f;
        #pragma unroll
        for (int j = 0; j < F_; j++) {
            float wj = 0.f;
            #pragma unroll
            for (int i = 0; i < F_; i++) wj += Sig[i * F_ + j] * W1[i * H1 + c];
            bacc += mu[j] * wj;
        }
        sB1[c] = b1[c] - bacc;
    }
    for (int m = tid; m < H1 * H2; m += THREADS) sW2[m] = W2[m];
    if (tid < H2) sB2[tid] = b2[tid];
    if (tid < H2) sW3[tid] = W3[tid];
    __syncthreads();

    const float b3v = b3[0];
    const int rowsBeg = k * ROWS_CTA;
    const int rowsEnd = (rowsBeg + ROWS_CTA < ROWS_S) ? rowsBeg + ROWS_CTA : ROWS_S;
    float* outS = out + s * ROWS_S;
    const char* obsB = (const char*)sObs;

    int idx0 = rowsBeg + tid;
    if (idx0 >= rowsEnd) return;

    RowIdx ra[R_];
    #pragma unroll
    for (int r = 0; r < R_; r++) {
        int id = idx0 + r * THREADS;
        ra[r] = load_idx(perm, s, id < rowsEnd ? id : rowsEnd - 1);
    }

    while (true) {
        const int curBase = idx0;
        RowIdx ci[R_];
        #pragma unroll
        for (int r = 0; r < R_; r++) ci[r] = ra[r];

        // ---- prefetch next iteration's perm indices ----
        idx0 += R_ * THREADS;
        const bool more = (idx0 < rowsEnd);
        if (more) {
            #pragma unroll
            for (int r = 0; r < R_; r++) {
                int id = idx0 + r * THREADS;
                ra[r] = load_idx(perm, s, id < rowsEnd ? id : rowsEnd - 1);
            }
        }

        // ---- layer-2 accumulators (init with b2) ----
        ull c2[R_][8];
        {
            const ull* pb = (const ull*)sB2;
            #pragma unroll
            for (int r = 0; r < R_; r++)
                #pragma unroll
                for (int p = 0; p < 8; p++) c2[r][p] = pb[p];
        }

        // ---- layer 1 in two 16-wide halves, group-wise gather ----
        #pragma unroll
        for (int half = 0; half < 2; half++) {
            ull h[R_][8];
            {
                const ull* pb = (const ull*)(sB1 + half * 16);
                #pragma unroll
                for (int r = 0; r < R_; r++)
                    #pragma unroll
                    for (int p = 0; p < 8; p++) h[r][p] = pb[p];
            }
            #pragma unroll
            for (int g = 0; g < G_; g++) {
                float4 xg[R_];
                #pragma unroll
                for (int r = 0; r < R_; r++)
                    xg[r] = *(const float4*)(obsB + ci[r].off[g] + g * 16);
                #pragma unroll
                for (int jj = 0; jj < 4; jj++) {
                    const ulonglong2* w =
                        (const ulonglong2*)(sW1 + (4 * g + jj) * H1 + half * 16);
                    ulonglong2 w0 = w[0], w1 = w[1], w2 = w[2], w3 = w[3];
                    #pragma unroll
                    for (int r = 0; r < R_; r++) {
                        const float* xp = (const float*)&xg[r];
                        ull xj = pk2(xp[jj], xp[jj]);
                        h[r][0] = fma2(xj, w0.x, h[r][0]);
                        h[r][1] = fma2(xj, w0.y, h[r][1]);
                        h[r][2] = fma2(xj, w1.x, h[r][2]);
                        h[r][3] = fma2(xj, w1.y, h[r][3]);
                        h[r][4] = fma2(xj, w2.x, h[r][4]);
                        h[r][5] = fma2(xj, w2.y, h[r][5]);
                        h[r][6] = fma2(xj, w3.x, h[r][6]);
                        h[r][7] = fma2(xj, w3.y, h[r][7]);
                    }
                }
            }
            // ---- lrelu + layer-2 accumulation ----
            #pragma unroll
            for (int p = 0; p < 8; p++) {
                int i0 = half * 16 + 2 * p;
                const ulonglong2* wu = (const ulonglong2*)(sW2 + i0 * H2);
                const ulonglong2* wv = (const ulonglong2*)(sW2 + (i0 + 1) * H2);
                ulonglong2 u0 = wu[0], u1 = wu[1], u2 = wu[2], u3 = wu[3];
                ulonglong2 v0 = wv[0], v1 = wv[1], v2 = wv[2], v3 = wv[3];
                #pragma unroll
                for (int r = 0; r < R_; r++) {
                    float a, b;
                    upk(h[r][p], a, b);
                    float au = lrelu(a), av = lrelu(b);
                    ull au2 = pk2(au, au), av2 = pk2(av, av);
                    c2[r][0] = fma2(au2, u0.x, c2[r][0]);
                    c2[r][1] = fma2(au2, u0.y, c2[r][1]);
                    c2[r][2] = fma2(au2, u1.x, c2[r][2]);
                    c2[r][3] = fma2(au2, u1.y, c2[r][3]);
                    c2[r][4] = fma2(au2, u2.x, c2[r][4]);
                    c2[r][5] = fma2(au2, u2.y, c2[r][5]);
                    c2[r][6] = fma2(au2, u3.x, c2[r][6]);
                    c2[r][7] = fma2(au2, u3.y, c2[r][7]);
                    c2[r][0] = fma2(av2, v0.x, c2[r][0]);
                    c2[r][1] = fma2(av2, v0.y, c2[r][1]);
                    c2[r][2] = fma2(av2, v1.x, c2[r][2]);
                    c2[r][3] = fma2(av2, v1.y, c2[r][3]);
                    c2[r][4] = fma2(av2, v2.x, c2[r][4]);
                    c2[r][5] = fma2(av2, v2.y, c2[r][5]);
                    c2[r][6] = fma2(av2, v3.x, c2[r][6]);
                    c2[r][7] = fma2(av2, v3.y, c2[r][7]);
                }
            }
        }

        // ---- layer 3 + sigmoid + guarded store ----
        #pragma unroll
        for (int r = 0; r < R_; r++) {
            float z0 = b3v, z1 = 0.f;
            #pragma unroll
            for (int p = 0; p < 8; p++) {
                float u, v;
                upk(c2[r][p], u, v);
                z0 += lrelu(u) * sW3[2 * p];
                z1 += lrelu(v) * sW3[2 * p + 1];
            }
            float z = z0 + z1;
            int cid = curBase + r * THREADS;
            if (cid < rowsEnd) outS[cid] = 1.f / (1.f + __expf(-z));
        }

        if (!more) break;
    }
}

extern "C" void kernel_launch(void* const* d_in, const int* in_sizes, int n_in,
                              void* d_out, int out_size) {
    const float* obs  = (const float*)d_in[0];
    const float* mu   = (const float*)d_in[1];
    const float* Sig  = (const float*)d_in[2];
    const int*   perm = (const int*)d_in[3];
    const float* W1   = (const float*)d_in[4];
    const float* b1   = (const float*)d_in[5];
    const float* W2   = (const float*)d_in[6];
    const float* b2   = (const float*)d_in[7];
    const float* W3   = (const float*)d_in[8];
    const float* b3   = (const float*)d_in[9];
    float* out = (float*)d_out;

    dim3 grid(CHUNKS, S_);
    fused_kernel<<<grid, THREADS>>>(obs, mu, Sig, perm, W1, b1, W2, b2, W3, b3, out);
}

// round 13
// speedup vs baseline: 1.0482x; 1.0166x over previous
#include <cuda_runtime.h>
#include <cstdint>

#define S_  16
#define T_  400
#define F_  16
#define SF_ 250
#define G_  4
#define H1  32
#define H2  16

#define OBS_STRIDE 20
#define THREADS    256
#define R_         4
#define CHUNKS     9
#define ROWS_S     (T_ * (SF_ + 1))                    // 100400
#define ROWS_CTA   ((ROWS_S + CHUNKS - 1) / CHUNKS)    // 11156

typedef unsigned long long ull;

__device__ __forceinline__ ull pk2(float a, float b) {
    ull r; asm("mov.b64 %0, {%1,%2};" : "=l"(r) : "f"(a), "f"(b)); return r;
}
__device__ __forceinline__ void upk(ull p, float& a, float& b) {
    asm("mov.b64 {%0,%1}, %2;" : "=f"(a), "=f"(b) : "l"(p));
}
__device__ __forceinline__ ull fma2(ull a, ull b, ull c) {
    ull d; asm("fma.rn.f32x2 %0, %1, %2, %3;" : "=l"(d) : "l"(a), "l"(b), "l"(c)); return d;
}
__device__ __forceinline__ ull mul2(ull a, ull b) {
    ull d; asm("mul.rn.f32x2 %0, %1, %2;" : "=l"(d) : "l"(a), "l"(b)); return d;
}
__device__ __forceinline__ float lrelu(float x) { return fmaxf(x, 0.01f * x); }
// packed leaky-relu: lrelu(x) = 0.505x + 0.495|x|  (x>0 -> x, x<0 -> 0.01x)
__device__ __forceinline__ ull lrelu2(ull x, ull c505, ull c495) {
    ull ax = x & 0x7FFFFFFF7FFFFFFFull;     // 2x LOP3 on alu pipe
    return fma2(ax, c495, mul2(x, c505));
}

struct RowIdx { int t[G_]; };

__device__ __forceinline__ RowIdx load_idx(const int* __restrict__ perm, int s, int idx) {
    RowIdx r;
    int sfp = idx / T_;
    int t   = idx - sfp * T_;
    if (sfp == 0) { r.t[0] = r.t[1] = r.t[2] = r.t[3] = t; }
    else {
        int base = ((sfp - 1) * (G_ * S_) + s) * T_ + t;
        r.t[0] = perm[base];
        r.t[1] = perm[base + S_ * T_];
        r.t[2] = perm[base + 2 * S_ * T_];
        r.t[3] = perm[base + 3 * S_ * T_];
    }
    return r;
}

__global__ __launch_bounds__(THREADS, 1)
void fused_kernel(const float* __restrict__ obs,
                  const float* __restrict__ mu,
                  const float* __restrict__ Sig,
                  const int*   __restrict__ perm,
                  const float* __restrict__ W1,
                  const float* __restrict__ b1,
                  const float* __restrict__ W2,
                  const float* __restrict__ b2,
                  const float* __restrict__ W3,
                  const float* __restrict__ b3,
                  float* __restrict__ out) {
    __shared__ __align__(16) float sObs[T_ * OBS_STRIDE];  // 32000 B
    __shared__ __align__(16) float sW1[F_ * H1];           // W1eff [j][c]
    __shared__ __align__(16) float sW2[H1 * H2];           // [i][j]
    __shared__ __align__(16) float sB1[H1];
    __shared__ __align__(16) float sB2[H2];
    __shared__ __align__(16) float sW3[H2];

    const int s   = blockIdx.y;
    const int k   = blockIdx.x;
    const int tid = threadIdx.x;

    // ---- stage obs slice (padded rows) ----
    const float4* osrc = (const float4*)(obs + s * (T_ * F_));
    for (int m = tid; m < T_ * F_ / 4; m += THREADS) {
        int t = m >> 2, q = m & 3;
        *(float4*)(sObs + t * OBS_STRIDE + q * 4) = osrc[m];
    }
    // ---- W1eff = Sigma^T W1 (normalize folded into layer 1) ----
    for (int m = tid; m < F_ * H1; m += THREADS) {
        int j = m >> 5, c = m & 31;
        float acc = 0.f;
        #pragma unroll
        for (int i = 0; i < F_; i++) acc += Sig[i * F_ + j] * W1[i * H1 + c];
        sW1[j * H1 + c] = acc;
    }
    // ---- b1eff = b1 - mu^T W1eff ----
    if (tid < H1) {
        int c = tid;
        float bacc = 0.f;
        #pragma unroll
        for (int j = 0; j < F_; j++) {
            float wj = 0.f;
            #pragma unroll
            for (int i = 0; i < F_; i++) wj += Sig[i * F_ + j] * W1[i * H1 + c];
            bacc += mu[j] * wj;
        }
        sB1[c] = b1[c] - bacc;
    }
    for (int m = tid; m < H1 * H2; m += THREADS) sW2[m] = W2[m];
    if (tid < H2) sB2[tid] = b2[tid];
    if (tid < H2) sW3[tid] = W3[tid];
    __syncthreads();

    const float b3v = b3[0];
    const int rowsBeg = k * ROWS_CTA;
    const int rowsEnd = (rowsBeg + ROWS_CTA < ROWS_S) ? rowsBeg + ROWS_CTA : ROWS_S;
    float* outS = out + s * ROWS_S;

    const ull c505 = pk2(0.505f, 0.505f);
    const ull c495 = pk2(0.495f, 0.495f);

    int idx0 = rowsBeg + tid;
    if (idx0 >= rowsEnd) return;

    // prime prefetch (clamp duplicates; stores are guarded later)
    RowIdx ra[R_];
    #pragma unroll
    for (int r = 0; r < R_; r++) {
        int id = idx0 + r * THREADS;
        ra[r] = load_idx(perm, s, id < rowsEnd ? id : rowsEnd - 1);
    }

    while (true) {
        const int curBase = idx0;
        RowIdx ci[R_];
        #pragma unroll
        for (int r = 0; r < R_; r++) ci[r] = ra[r];

        // ---- prefetch next iteration's perm indices ----
        idx0 += R_ * THREADS;
        const bool more = (idx0 < rowsEnd);
        if (more) {
            #pragma unroll
            for (int r = 0; r < R_; r++) {
                int id = idx0 + r * THREADS;
                ra[r] = load_idx(perm, s, id < rowsEnd ? id : rowsEnd - 1);
            }
        }

        // ---- layer-2 accumulators (init with b2) ----
        ull c2[R_][8];
        {
            const ull* pb = (const ull*)sB2;
            #pragma unroll
            for (int r = 0; r < R_; r++)
                #pragma unroll
                for (int p = 0; p < 8; p++) c2[r][p] = pb[p];
        }

        // ---- layer 1 in two 16-wide halves, group-wise gather ----
        #pragma unroll
        for (int half = 0; half < 2; half++) {
            ull h[R_][8];
            {
                const ull* pb = (const ull*)(sB1 + half * 16);
                #pragma unroll
                for (int r = 0; r < R_; r++)
                    #pragma unroll
                    for (int p = 0; p < 8; p++) h[r][p] = pb[p];
            }
            #pragma unroll
            for (int g = 0; g < G_; g++) {
                float4 xg[R_];
                #pragma unroll
                for (int r = 0; r < R_; r++)
                    xg[r] = *(const float4*)(sObs + ci[r].t[g] * OBS_STRIDE + g * 4);
                #pragma unroll
                for (int jj = 0; jj < 4; jj++) {
                    const ulonglong2* w =
                        (const ulonglong2*)(sW1 + (4 * g + jj) * H1 + half * 16);
                    ulonglong2 w0 = w[0], w1 = w[1], w2 = w[2], w3 = w[3];
                    #pragma unroll
                    for (int r = 0; r < R_; r++) {
                        const float* xp = (const float*)&xg[r];
                        ull xj = pk2(xp[jj], xp[jj]);
                        h[r][0] = fma2(xj, w0.x, h[r][0]);
                        h[r][1] = fma2(xj, w0.y, h[r][1]);
                        h[r][2] = fma2(xj, w1.x, h[r][2]);
                        h[r][3] = fma2(xj, w1.y, h[r][3]);
                        h[r][4] = fma2(xj, w2.x, h[r][4]);
                        h[r][5] = fma2(xj, w2.y, h[r][5]);
                        h[r][6] = fma2(xj, w3.x, h[r][6]);
                        h[r][7] = fma2(xj, w3.y, h[r][7]);
                    }
                }
            }
            // ---- packed lrelu + layer-2 accumulation ----
            #pragma unroll
            for (int p = 0; p < 8; p++) {
                int i0 = half * 16 + 2 * p;
                const ulonglong2* wu = (const ulonglong2*)(sW2 + i0 * H2);
                const ulonglong2* wv = (const ulonglong2*)(sW2 + (i0 + 1) * H2);
                ulonglong2 u0 = wu[0], u1 = wu[1], u2 = wu[2], u3 = wu[3];
                ulonglong2 v0 = wv[0], v1 = wv[1], v2 = wv[2], v3 = wv[3];
                #pragma unroll
                for (int r = 0; r < R_; r++) {
                    ull lr = lrelu2(h[r][p], c505, c495);   // packed: 2 fma-ops + 2 alu
                    float au, av;
                    upk(lr, au, av);
                    ull au2 = pk2(au, au), av2 = pk2(av, av);
                    c2[r][0] = fma2(au2, u0.x, c2[r][0]);
                    c2[r][1] = fma2(au2, u0.y, c2[r][1]);
                    c2[r][2] = fma2(au2, u1.x, c2[r][2]);
                    c2[r][3] = fma2(au2, u1.y, c2[r][3]);
                    c2[r][4] = fma2(au2, u2.x, c2[r][4]);
                    c2[r][5] = fma2(au2, u2.y, c2[r][5]);
                    c2[r][6] = fma2(au2, u3.x, c2[r][6]);
                    c2[r][7] = fma2(au2, u3.y, c2[r][7]);
                    c2[r][0] = fma2(av2, v0.x, c2[r][0]);
                    c2[r][1] = fma2(av2, v0.y, c2[r][1]);
                    c2[r][2] = fma2(av2, v1.x, c2[r][2]);
                    c2[r][3] = fma2(av2, v1.y, c2[r][3]);
                    c2[r][4] = fma2(av2, v2.x, c2[r][4]);
                    c2[r][5] = fma2(av2, v2.y, c2[r][5]);
                    c2[r][6] = fma2(av2, v3.x, c2[r][6]);
                    c2[r][7] = fma2(av2, v3.y, c2[r][7]);
                }
            }
        }

        // ---- layer 3 (packed) + sigmoid + guarded store ----
        const ull* w3p = (const ull*)sW3;   // 8 packed pairs
        #pragma unroll
        for (int r = 0; r < R_; r++) {
            ull zp = 0;
            #pragma unroll
            for (int p = 0; p < 8; p++) {
                ull lr = lrelu2(c2[r][p], c505, c495);
                zp = fma2(lr, w3p[p], zp);
            }
            float z0, z1;
            upk(zp, z0, z1);
            float z = b3v + z0 + z1;
            int cid = curBase + r * THREADS;
            if (cid < rowsEnd) outS[cid] = 1.f / (1.f + __expf(-z));
        }

        if (!more) break;
    }
}

extern "C" void kernel_launch(void* const* d_in, const int* in_sizes, int n_in,
                              void* d_out, int out_size) {
    const float* obs  = (const float*)d_in[0];
    const float* mu   = (const float*)d_in[1];
    const float* Sig  = (const float*)d_in[2];
    const int*   perm = (const int*)d_in[3];
    const float* W1   = (const float*)d_in[4];
    const float* b1   = (const float*)d_in[5];
    const float* W2   = (const float*)d_in[6];
    const float* b2   = (const float*)d_in[7];
    const float* W3   = (const float*)d_in[8];
    const float* b3   = (const float*)d_in[9];
    float* out = (float*)d_out;

    dim3 grid(CHUNKS, S_);
    fused_kernel<<<grid, THREADS>>>(obs, mu, Sig, perm, W1, b1, W2, b2, W3, b3, out);
}